// round 14
// baseline (speedup 1.0000x reference)
#include <cuda_runtime.h>
#include <cuda_bf16.h>

#define KDIM 256
#define TEMPF 1.0e8f
#define RPB 256          // rows per block (1 thread per row in phase 1)
#define MAXC 8           // max window candidates per row
#define NB 64            // value buckets over [-1/256, 1/256]
#define B0 (-0.00390625f)            // -1/256
#define BW (1.220703125e-4f)         // (2/256)/64

__device__ __forceinline__ int bucket_of(float v)
{
    int b = (int)((v - B0) * 8192.0f);   // 1/BW = 8192
    return min(NB - 1, max(0, b));
}

// Correctly-rounded (to ~2^-39 before final rounding) float exp for r in [-80, 0].
__device__ __forceinline__ float exp_cr(float r, const double* __restrict__ T)
{
    float nf = rintf(r * 46.166241f);                 // r * 32/ln2
    int n2 = (int)nf;
    int m  = n2 >> 5;
    int j  = n2 & 31;
    double fd = fma((double)nf, -2.1660849392498290e-2, (double)r);  // r - nf*ln2/32
    double p  = fma(fd, 1.0 / 24.0, 1.0 / 6.0);
    p = fma(fd, p, 0.5);
    p = fma(fd, p, 1.0);
    p = fma(fd, p, 1.0);
    float sf = (float)(T[j] * p);
    return sf * __int_as_float((m + 127) << 23);
}

__global__ __launch_bounds__(256, 8) void quantizer_kernel(
    const float* __restrict__ x,      // (rows)
    const float* __restrict__ cb,     // (256)
    float* __restrict__ soft,         // (rows, 256)
    float* __restrict__ hard,         // (rows, 256)
    float* __restrict__ quant,        // (rows)
    int rows)
{
    __shared__ int    scnt[NB];
    __shared__ int    sstart[NB + 1];
    __shared__ int    scur[NB];
    __shared__ float  bval[KDIM];               // bucket-grouped values
    __shared__ short  bkk [KDIM];               // bucket-grouped original k
    __shared__ double Texp[32];
    __shared__ short  s_bk[RPB];
    __shared__ char   s_n [RPB];
    __shared__ short  s_idx[RPB][MAXC];
    __shared__ float  s_val[RPB][MAXC];

    const int tid  = threadIdx.x;
    const int row0 = blockIdx.x * RPB;
    const int row  = row0 + tid;

    // Issue x load first so it overlaps the bucket build.
    const float xv = (row < rows) ? x[row] : 0.0f;
    const float cv_own = cb[tid];

    if (tid < NB) scnt[tid] = 0;
    if (tid < 32) Texp[tid] = exp2((double)tid * 0.03125);
    __syncthreads();

    const int myb = bucket_of(cv_own);
    atomicAdd(&scnt[myb], 1);
    __syncthreads();

    // Exclusive scan over 64 counts, warp 0 only (2 elems/lane, shfl scan).
    if (tid < 32) {
        int c0 = scnt[tid], c1 = scnt[tid + 32];
        int p0 = c0, p1 = c1;
#pragma unroll
        for (int off = 1; off < 32; off <<= 1) {
            int t0 = __shfl_up_sync(0xFFFFFFFFu, p0, off);
            int t1 = __shfl_up_sync(0xFFFFFFFFu, p1, off);
            if ((tid & 31) >= off) { p0 += t0; p1 += t1; }
        }
        int tot0 = __shfl_sync(0xFFFFFFFFu, p0, 31);   // sum of first 32 buckets
        sstart[tid]      = p0 - c0;                    // exclusive
        sstart[tid + 32] = tot0 + p1 - c1;
        scur[tid]        = p0 - c0;
        scur[tid + 32]   = tot0 + p1 - c1;
        if (tid == 31) sstart[NB] = KDIM;
    }
    __syncthreads();

    {   // scatter (order within bucket nondeterministic -> fixed by k-sort later)
        int pos = atomicAdd(&scur[myb], 1);
        bval[pos] = cv_own;
        bkk [pos] = (short)tid;
    }
    __syncthreads();

    // ---------------- Phase 1: thread-per-row sparse compute ----------------
    if (row < rows) {
        // nearest-neighbor via expanding bucket scan
        const int bx = bucket_of(xv);
        float best = 3.0e38f;
        for (int p = sstart[bx]; p < sstart[bx + 1]; p++)
            best = fminf(best, fabsf(xv - bval[p]));
        int l = bx - 1, r = bx + 1;
        while (true) {
            float dl = (l >= 0) ? (xv - (B0 + (float)(l + 1) * BW)) : 3.0e38f;
            float dr = (r < NB) ? ((B0 + (float)r * BW) - xv)       : 3.0e38f;
            if (dl <= dr) {
                if (dl > best + 4e-9f) break;          // fuzz-padded prune
                for (int p = sstart[l]; p < sstart[l + 1]; p++)
                    best = fminf(best, fabsf(xv - bval[p]));
                l--;
            } else {
                if (dr > best + 4e-9f) break;
                for (int p = sstart[r]; p < sstart[r + 1]; p++)
                    best = fminf(best, fabsf(xv - bval[p]));
                r++;
            }
        }
        const float amin = best;

        // window: t = 1e8*(d - dmax) >= ~-24  <=>  a <= amin + ~2.2e-7/dmax
        const float d_est = __expf(-amin);
        const float wthr  = amin + 2.2e-7f / d_est;

        // collect candidates from buckets overlapping [xv-wthr, xv+wthr]
        int   nc = 0;
        float avs[MAXC], cvs[MAXC];
        short kks[MAXC];
        const int bL = bucket_of(xv - wthr - 1e-8f);
        const int bR = bucket_of(xv + wthr + 1e-8f);
        for (int b = bL; b <= bR; b++)
            for (int p = sstart[b]; p < sstart[b + 1]; p++) {
                float cv = bval[p];
                float a  = fabsf(xv - cv);
                if (a <= wthr && nc < MAXC) {
                    avs[nc] = a; cvs[nc] = cv; kks[nc] = bkk[p]; nc++;
                }
            }

        // sort candidates by original k (nc <= 8; deterministic sum order)
        for (int i = 1; i < nc; i++) {
            short ki = kks[i]; float ai = avs[i], ci = cvs[i];
            int j = i - 1;
            while (j >= 0 && kks[j] > ki) {
                kks[j + 1] = kks[j]; avs[j + 1] = avs[j]; cvs[j + 1] = cvs[j];
                j--;
            }
            kks[j + 1] = ki; avs[j + 1] = ai; cvs[j + 1] = ci;
        }

        // accurate d on candidates; argmax with lowest-ORIGINAL-k tie-break
        float dcand[MAXC];
        float bd = -1.0f; int bk = 0;
        for (int i = 0; i < nc; i++) {
            float di = exp_cr(-avs[i], Texp);
            dcand[i] = di;
            int ki = kks[i];
            if (di > bd || (di == bd && ki < bk)) { bd = di; bk = ki; }
        }

        // softmax(TEMP*d): scale-then-subtract exactly like jax.nn.softmax
        const float amax = __fmul_rn(TEMPF, bd);
        float sum = 0.0f, qp = 0.0f;
        float sv[MAXC];
        for (int i = 0; i < nc; i++) {
            float t = __fadd_rn(__fmul_rn(TEMPF, dcand[i]), -amax);
            float s = __expf(t);
            sv[i] = s;
            sum += s;
            qp  = __fmaf_rn(s, cvs[i], qp);
        }
        const float inv = 1.0f / sum;
        __stcs(quant + row, qp * inv);

        s_bk[tid] = (short)bk;
        s_n [tid] = (char)nc;
        for (int i = 0; i < nc; i++) {
            s_idx[tid][i] = kks[i];
            s_val[tid][i] = sv[i] * inv;
        }
    } else {
        s_n[tid] = 0; s_bk[tid] = -1;
    }
    __syncthreads();

    // ---------------- Phase 2: warp-per-row dense streaming stores ----------------
    // Hard one-hot folded into the candidate loop: bk is always a candidate
    // (its distance == amin <= wthr), so the shared position-ISETPs drive both
    // the soft SELs (vi) and the hard SELs (hb). One row in flight: 8 live
    // float4 accumulators, same register class as before -> no spills.
    const int lane = tid & 31;
    const int warp = tid >> 5;
    const int k0 = 4 * lane;          // entries k0..k0+3
    const int k1 = 128 + 4 * lane;    // entries k1..k1+3

    for (int rr = warp; rr < RPB; rr += 8) {
        const int grow = row0 + rr;
        if (grow >= rows) break;
        const int n  = s_n[rr];
        const int bk = s_bk[rr];
        const size_t base = (size_t)grow * KDIM;

        float4 sv0 = make_float4(0.f, 0.f, 0.f, 0.f);
        float4 sv1 = make_float4(0.f, 0.f, 0.f, 0.f);
        float4 hv0 = make_float4(0.f, 0.f, 0.f, 0.f);
        float4 hv1 = make_float4(0.f, 0.f, 0.f, 0.f);
        for (int i = 0; i < n; i++) {
            const int   ki = s_idx[rr][i];     // LDS broadcast
            const float vi = s_val[rr][i];
            const float hb = (ki == bk) ? 1.0f : 0.0f;
            const bool m0 = (ki == k0    ), m1 = (ki == k0 + 1),
                       m2 = (ki == k0 + 2), m3 = (ki == k0 + 3);
            const bool m4 = (ki == k1    ), m5 = (ki == k1 + 1),
                       m6 = (ki == k1 + 2), m7 = (ki == k1 + 3);
            sv0.x = m0 ? vi : sv0.x;  hv0.x = m0 ? hb : hv0.x;
            sv0.y = m1 ? vi : sv0.y;  hv0.y = m1 ? hb : hv0.y;
            sv0.z = m2 ? vi : sv0.z;  hv0.z = m2 ? hb : hv0.z;
            sv0.w = m3 ? vi : sv0.w;  hv0.w = m3 ? hb : hv0.w;
            sv1.x = m4 ? vi : sv1.x;  hv1.x = m4 ? hb : hv1.x;
            sv1.y = m5 ? vi : sv1.y;  hv1.y = m5 ? hb : hv1.y;
            sv1.z = m6 ? vi : sv1.z;  hv1.z = m6 ? hb : hv1.z;
            sv1.w = m7 ? vi : sv1.w;  hv1.w = m7 ? hb : hv1.w;
        }

        // Streaming (evict-first) stores: output is write-once, never re-read.
        __stcs(reinterpret_cast<float4*>(soft + base) + lane,       sv0);
        __stcs(reinterpret_cast<float4*>(soft + base + 128) + lane, sv1);
        __stcs(reinterpret_cast<float4*>(hard + base) + lane,       hv0);
        __stcs(reinterpret_cast<float4*>(hard + base + 128) + lane, hv1);
    }
}

extern "C" void kernel_launch(void* const* d_in, const int* in_sizes, int n_in,
                              void* d_out, int out_size)
{
    const float* x  = (const float*)d_in[0];   // inputs (1024,512) f32
    const float* cb = (const float*)d_in[1];   // codebook (1,256) f32
    const int rows  = in_sizes[0];             // 524288

    float* out   = (float*)d_out;              // [soft | hard | quantized]
    float* soft  = out;
    float* hard  = out + (size_t)rows * KDIM;
    float* quant = out + 2ull * (size_t)rows * KDIM;

    const int blocks = (rows + RPB - 1) / RPB;
    quantizer_kernel<<<blocks, 256>>>(x, cb, soft, hard, quant, rows);
}

// round 15
// speedup vs baseline: 1.0107x; 1.0107x over previous
#include <cuda_runtime.h>
#include <cuda_bf16.h>

#define KDIM 256
#define TEMPF 1.0e8f
#define RPB 256          // rows per block (1 thread per row in phase 1)
#define MAXC 8           // max window candidates per row
#define NB 64            // value buckets over [-1/256, 1/256]
#define B0 (-0.00390625f)            // -1/256
#define BW (1.220703125e-4f)         // (2/256)/64

__device__ __forceinline__ int bucket_of(float v)
{
    int b = (int)((v - B0) * 8192.0f);   // 1/BW = 8192
    return min(NB - 1, max(0, b));
}

// Correctly-rounded (to ~2^-39 before final rounding) float exp for r in [-80, 0].
__device__ __forceinline__ float exp_cr(float r, const double* __restrict__ T)
{
    float nf = rintf(r * 46.166241f);                 // r * 32/ln2
    int n2 = (int)nf;
    int m  = n2 >> 5;
    int j  = n2 & 31;
    double fd = fma((double)nf, -2.1660849392498290e-2, (double)r);  // r - nf*ln2/32
    double p  = fma(fd, 1.0 / 24.0, 1.0 / 6.0);
    p = fma(fd, p, 0.5);
    p = fma(fd, p, 1.0);
    p = fma(fd, p, 1.0);
    float sf = (float)(T[j] * p);
    return sf * __int_as_float((m + 127) << 23);
}

__global__ __launch_bounds__(256, 8) void quantizer_kernel(
    const float* __restrict__ x,      // (rows)
    const float* __restrict__ cb,     // (256)
    float* __restrict__ soft,         // (rows, 256)
    float* __restrict__ hard,         // (rows, 256)
    float* __restrict__ quant,        // (rows)
    int rows)
{
    __shared__ int    scnt[NB];
    __shared__ int    sstart[NB + 1];
    __shared__ int    scur[NB];
    __shared__ float  bval[KDIM];               // bucket-grouped values
    __shared__ short  bkk [KDIM];               // bucket-grouped original k
    __shared__ double Texp[32];
    __shared__ float  wmin[8], wmax[8];         // per-warp partial reductions
    __shared__ float  s_cbmin, s_cbmax;
    __shared__ short  s_bk[RPB];
    __shared__ char   s_n [RPB];
    __shared__ short  s_idx[RPB][MAXC];
    __shared__ float  s_val[RPB][MAXC];

    const int tid  = threadIdx.x;
    const int row0 = blockIdx.x * RPB;
    const int row  = row0 + tid;

    // Issue x load first so it overlaps the bucket build.
    const float xv = (row < rows) ? x[row] : 0.0f;
    const float cv_own = cb[tid];

    if (tid < NB) scnt[tid] = 0;
    if (tid < 32) Texp[tid] = exp2((double)tid * 0.03125);

    // Block min/max of codebook (warp shfl reduce + cross-warp reduce).
    {
        float mn = cv_own, mx = cv_own;
#pragma unroll
        for (int off = 16; off; off >>= 1) {
            mn = fminf(mn, __shfl_xor_sync(0xFFFFFFFFu, mn, off));
            mx = fmaxf(mx, __shfl_xor_sync(0xFFFFFFFFu, mx, off));
        }
        if ((tid & 31) == 0) { wmin[tid >> 5] = mn; wmax[tid >> 5] = mx; }
    }
    __syncthreads();
    if (tid == 0) {
        float mn = wmin[0], mx = wmax[0];
#pragma unroll
        for (int w = 1; w < 8; w++) { mn = fminf(mn, wmin[w]); mx = fmaxf(mx, wmax[w]); }
        s_cbmin = mn; s_cbmax = mx;
    }

    const int myb = bucket_of(cv_own);
    atomicAdd(&scnt[myb], 1);
    __syncthreads();

    // Exclusive scan over 64 counts, warp 0 only (2 elems/lane, shfl scan).
    if (tid < 32) {
        int c0 = scnt[tid], c1 = scnt[tid + 32];
        int p0 = c0, p1 = c1;
#pragma unroll
        for (int off = 1; off < 32; off <<= 1) {
            int t0 = __shfl_up_sync(0xFFFFFFFFu, p0, off);
            int t1 = __shfl_up_sync(0xFFFFFFFFu, p1, off);
            if ((tid & 31) >= off) { p0 += t0; p1 += t1; }
        }
        int tot0 = __shfl_sync(0xFFFFFFFFu, p0, 31);   // sum of first 32 buckets
        sstart[tid]      = p0 - c0;                    // exclusive
        sstart[tid + 32] = tot0 + p1 - c1;
        scur[tid]        = p0 - c0;
        scur[tid + 32]   = tot0 + p1 - c1;
        if (tid == 31) sstart[NB] = KDIM;
    }
    __syncthreads();

    {   // scatter (order within bucket nondeterministic -> fixed by k-sort later)
        int pos = atomicAdd(&scur[myb], 1);
        bval[pos] = cv_own;
        bkk [pos] = (short)tid;
    }
    __syncthreads();

    // ---------------- Phase 1: thread-per-row sparse compute ----------------
    if (row < rows) {
        // amin: fast path for xv outside the codebook range (~99.7% of rows):
        // nearest entry is the extreme value, no search needed.
        float amin;
        if (xv >= s_cbmax) {
            amin = xv - s_cbmax;
        } else if (xv <= s_cbmin) {
            amin = s_cbmin - xv;
        } else {
            // expanding bucket scan (in-range rows only)
            const int bx = bucket_of(xv);
            float best = 3.0e38f;
            for (int p = sstart[bx]; p < sstart[bx + 1]; p++)
                best = fminf(best, fabsf(xv - bval[p]));
            int l = bx - 1, r = bx + 1;
            while (true) {
                float dl = (l >= 0) ? (xv - (B0 + (float)(l + 1) * BW)) : 3.0e38f;
                float dr = (r < NB) ? ((B0 + (float)r * BW) - xv)       : 3.0e38f;
                if (dl <= dr) {
                    if (dl > best + 4e-9f) break;          // fuzz-padded prune
                    for (int p = sstart[l]; p < sstart[l + 1]; p++)
                        best = fminf(best, fabsf(xv - bval[p]));
                    l--;
                } else {
                    if (dr > best + 4e-9f) break;
                    for (int p = sstart[r]; p < sstart[r + 1]; p++)
                        best = fminf(best, fabsf(xv - bval[p]));
                    r++;
                }
            }
            amin = best;
        }

        // window: t = 1e8*(d - dmax) >= ~-24  <=>  a <= amin + ~2.2e-7/dmax
        const float d_est = __expf(-amin);
        const float wthr  = amin + 2.2e-7f / d_est;

        // collect candidates from buckets overlapping [xv-wthr, xv+wthr]
        int   nc = 0;
        float avs[MAXC], cvs[MAXC];
        short kks[MAXC];
        const int bL = bucket_of(xv - wthr - 1e-8f);
        const int bR = bucket_of(xv + wthr + 1e-8f);
        for (int b = bL; b <= bR; b++)
            for (int p = sstart[b]; p < sstart[b + 1]; p++) {
                float cv = bval[p];
                float a  = fabsf(xv - cv);
                if (a <= wthr && nc < MAXC) {
                    avs[nc] = a; cvs[nc] = cv; kks[nc] = bkk[p]; nc++;
                }
            }

        // sort candidates by original k (nc <= 8; deterministic sum order)
        for (int i = 1; i < nc; i++) {
            short ki = kks[i]; float ai = avs[i], ci = cvs[i];
            int j = i - 1;
            while (j >= 0 && kks[j] > ki) {
                kks[j + 1] = kks[j]; avs[j + 1] = avs[j]; cvs[j + 1] = cvs[j];
                j--;
            }
            kks[j + 1] = ki; avs[j + 1] = ai; cvs[j + 1] = ci;
        }

        // accurate d on candidates; argmax with lowest-ORIGINAL-k tie-break
        float dcand[MAXC];
        float bd = -1.0f; int bk = 0;
        for (int i = 0; i < nc; i++) {
            float di = exp_cr(-avs[i], Texp);
            dcand[i] = di;
            int ki = kks[i];
            if (di > bd || (di == bd && ki < bk)) { bd = di; bk = ki; }
        }

        // softmax(TEMP*d): scale-then-subtract exactly like jax.nn.softmax
        const float amax = __fmul_rn(TEMPF, bd);
        float sum = 0.0f, qp = 0.0f;
        float sv[MAXC];
        for (int i = 0; i < nc; i++) {
            float t = __fadd_rn(__fmul_rn(TEMPF, dcand[i]), -amax);
            float s = __expf(t);
            sv[i] = s;
            sum += s;
            qp  = __fmaf_rn(s, cvs[i], qp);
        }
        const float inv = 1.0f / sum;
        __stcs(quant + row, qp * inv);

        s_bk[tid] = (short)bk;
        s_n [tid] = (char)nc;
        for (int i = 0; i < nc; i++) {
            s_idx[tid][i] = kks[i];
            s_val[tid][i] = sv[i] * inv;
        }
    } else {
        s_n[tid] = 0; s_bk[tid] = -1;
    }
    __syncthreads();

    // ---------------- Phase 2: warp-per-row dense streaming stores ----------------
    const int lane = tid & 31;
    const int warp = tid >> 5;
    const int k0 = 4 * lane;          // entries k0..k0+3
    const int k1 = 128 + 4 * lane;    // entries k1..k1+3

    for (int rr = warp; rr < RPB; rr += 8) {
        const int grow = row0 + rr;
        if (grow >= rows) break;
        const int n  = s_n[rr];
        const int bk = s_bk[rr];
        const size_t base = (size_t)grow * KDIM;

        float4 sv0 = make_float4(0.f, 0.f, 0.f, 0.f);
        float4 sv1 = make_float4(0.f, 0.f, 0.f, 0.f);
        for (int i = 0; i < n; i++) {
            const int   ki = s_idx[rr][i];     // LDS broadcast
            const float vi = s_val[rr][i];
            sv0.x = (ki == k0    ) ? vi : sv0.x;
            sv0.y = (ki == k0 + 1) ? vi : sv0.y;
            sv0.z = (ki == k0 + 2) ? vi : sv0.z;
            sv0.w = (ki == k0 + 3) ? vi : sv0.w;
            sv1.x = (ki == k1    ) ? vi : sv1.x;
            sv1.y = (ki == k1 + 1) ? vi : sv1.y;
            sv1.z = (ki == k1 + 2) ? vi : sv1.z;
            sv1.w = (ki == k1 + 3) ? vi : sv1.w;
        }
        float4 hv0 = make_float4(bk == k0     ? 1.f : 0.f,
                                 bk == k0 + 1 ? 1.f : 0.f,
                                 bk == k0 + 2 ? 1.f : 0.f,
                                 bk == k0 + 3 ? 1.f : 0.f);
        float4 hv1 = make_float4(bk == k1     ? 1.f : 0.f,
                                 bk == k1 + 1 ? 1.f : 0.f,
                                 bk == k1 + 2 ? 1.f : 0.f,
                                 bk == k1 + 3 ? 1.f : 0.f);

        // Streaming (evict-first) stores: output is write-once, never re-read.
        __stcs(reinterpret_cast<float4*>(soft + base) + lane,       sv0);
        __stcs(reinterpret_cast<float4*>(soft + base + 128) + lane, sv1);
        __stcs(reinterpret_cast<float4*>(hard + base) + lane,       hv0);
        __stcs(reinterpret_cast<float4*>(hard + base + 128) + lane, hv1);
    }
}

extern "C" void kernel_launch(void* const* d_in, const int* in_sizes, int n_in,
                              void* d_out, int out_size)
{
    const float* x  = (const float*)d_in[0];   // inputs (1024,512) f32
    const float* cb = (const float*)d_in[1];   // codebook (1,256) f32
    const int rows  = in_sizes[0];             // 524288

    float* out   = (float*)d_out;              // [soft | hard | quantized]
    float* soft  = out;
    float* hard  = out + (size_t)rows * KDIM;
    float* quant = out + 2ull * (size_t)rows * KDIM;

    const int blocks = (rows + RPB - 1) / RPB;
    quantizer_kernel<<<blocks, 256>>>(x, cb, soft, hard, quant, rows);
}

// round 16
// speedup vs baseline: 1.0293x; 1.0184x over previous
#include <cuda_runtime.h>
#include <cuda_bf16.h>

#define KDIM 256
#define TEMPF 1.0e8f
#define RPB 256          // rows per block (1 thread per row in phase 1)
#define MAXC 8           // max window candidates per row
#define NB 64            // value buckets over [-1/256, 1/256]
#define B0 (-0.00390625f)            // -1/256
#define BW (1.220703125e-4f)         // (2/256)/64

__device__ __forceinline__ int bucket_of(float v)
{
    int b = (int)((v - B0) * 8192.0f);   // 1/BW = 8192
    return min(NB - 1, max(0, b));
}

// Correctly-rounded (to ~2^-39 before final rounding) float exp for r in [-80, 0].
__device__ __forceinline__ float exp_cr(float r, const double* __restrict__ T)
{
    float nf = rintf(r * 46.166241f);                 // r * 32/ln2
    int n2 = (int)nf;
    int m  = n2 >> 5;
    int j  = n2 & 31;
    double fd = fma((double)nf, -2.1660849392498290e-2, (double)r);  // r - nf*ln2/32
    double p  = fma(fd, 1.0 / 24.0, 1.0 / 6.0);
    p = fma(fd, p, 0.5);
    p = fma(fd, p, 1.0);
    p = fma(fd, p, 1.0);
    float sf = (float)(T[j] * p);
    return sf * __int_as_float((m + 127) << 23);
}

__global__ __launch_bounds__(256, 8) void quantizer_kernel(
    const float* __restrict__ x,      // (rows)
    const float* __restrict__ cb,     // (256)
    float* __restrict__ soft,         // (rows, 256)
    float* __restrict__ hard,         // (rows, 256)
    float* __restrict__ quant,        // (rows)
    int rows)
{
    __shared__ int    scnt[NB];
    __shared__ int    sstart[NB + 1];
    __shared__ int    scur[NB];
    __shared__ float  bval[KDIM];               // bucket-grouped values
    __shared__ short  bkk [KDIM];               // bucket-grouped original k
    __shared__ double Texp[32];
    __shared__ int    s_meta[RPB];              // (bk << 16) | nc
    __shared__ int2   s_cand[RPB][MAXC];        // .x = ki, .y = float bits of value

    const int tid  = threadIdx.x;
    const int row0 = blockIdx.x * RPB;
    const int row  = row0 + tid;

    // Issue x load first so it overlaps the bucket build.
    const float xv = (row < rows) ? x[row] : 0.0f;
    const float cv_own = cb[tid];

    if (tid < NB) scnt[tid] = 0;
    if (tid < 32) Texp[tid] = exp2((double)tid * 0.03125);
    __syncthreads();

    const int myb = bucket_of(cv_own);
    atomicAdd(&scnt[myb], 1);
    __syncthreads();

    // Exclusive scan over 64 counts, warp 0 only (2 elems/lane, shfl scan).
    if (tid < 32) {
        int c0 = scnt[tid], c1 = scnt[tid + 32];
        int p0 = c0, p1 = c1;
#pragma unroll
        for (int off = 1; off < 32; off <<= 1) {
            int t0 = __shfl_up_sync(0xFFFFFFFFu, p0, off);
            int t1 = __shfl_up_sync(0xFFFFFFFFu, p1, off);
            if ((tid & 31) >= off) { p0 += t0; p1 += t1; }
        }
        int tot0 = __shfl_sync(0xFFFFFFFFu, p0, 31);   // sum of first 32 buckets
        sstart[tid]      = p0 - c0;                    // exclusive
        sstart[tid + 32] = tot0 + p1 - c1;
        scur[tid]        = p0 - c0;
        scur[tid + 32]   = tot0 + p1 - c1;
        if (tid == 31) sstart[NB] = KDIM;
    }
    __syncthreads();

    {   // scatter (order within bucket nondeterministic -> fixed by k-sort later)
        int pos = atomicAdd(&scur[myb], 1);
        bval[pos] = cv_own;
        bkk [pos] = (short)tid;
    }
    __syncthreads();

    // ---------------- Phase 1: thread-per-row sparse compute ----------------
    if (row < rows) {
        // nearest-neighbor via expanding bucket scan
        const int bx = bucket_of(xv);
        float best = 3.0e38f;
        for (int p = sstart[bx]; p < sstart[bx + 1]; p++)
            best = fminf(best, fabsf(xv - bval[p]));
        int l = bx - 1, r = bx + 1;
        while (true) {
            float dl = (l >= 0) ? (xv - (B0 + (float)(l + 1) * BW)) : 3.0e38f;
            float dr = (r < NB) ? ((B0 + (float)r * BW) - xv)       : 3.0e38f;
            if (dl <= dr) {
                if (dl > best + 4e-9f) break;          // fuzz-padded prune
                for (int p = sstart[l]; p < sstart[l + 1]; p++)
                    best = fminf(best, fabsf(xv - bval[p]));
                l--;
            } else {
                if (dr > best + 4e-9f) break;
                for (int p = sstart[r]; p < sstart[r + 1]; p++)
                    best = fminf(best, fabsf(xv - bval[p]));
                r++;
            }
        }
        const float amin = best;

        // window: t = 1e8*(d - dmax) >= ~-24  <=>  a <= amin + ~2.2e-7/dmax
        const float d_est = __expf(-amin);
        const float wthr  = amin + 2.2e-7f / d_est;

        // collect candidates from buckets overlapping [xv-wthr, xv+wthr]
        int   nc = 0;
        float avs[MAXC], cvs[MAXC];
        short kks[MAXC];
        const int bL = bucket_of(xv - wthr - 1e-8f);
        const int bR = bucket_of(xv + wthr + 1e-8f);
        for (int b = bL; b <= bR; b++)
            for (int p = sstart[b]; p < sstart[b + 1]; p++) {
                float cv = bval[p];
                float a  = fabsf(xv - cv);
                if (a <= wthr && nc < MAXC) {
                    avs[nc] = a; cvs[nc] = cv; kks[nc] = bkk[p]; nc++;
                }
            }

        // sort candidates by original k (nc <= 8; deterministic sum order)
        for (int i = 1; i < nc; i++) {
            short ki = kks[i]; float ai = avs[i], ci = cvs[i];
            int j = i - 1;
            while (j >= 0 && kks[j] > ki) {
                kks[j + 1] = kks[j]; avs[j + 1] = avs[j]; cvs[j + 1] = cvs[j];
                j--;
            }
            kks[j + 1] = ki; avs[j + 1] = ai; cvs[j + 1] = ci;
        }

        // accurate d on candidates; argmax with lowest-ORIGINAL-k tie-break
        float dcand[MAXC];
        float bd = -1.0f; int bk = 0;
        for (int i = 0; i < nc; i++) {
            float di = exp_cr(-avs[i], Texp);
            dcand[i] = di;
            int ki = kks[i];
            if (di > bd || (di == bd && ki < bk)) { bd = di; bk = ki; }
        }

        // softmax(TEMP*d): scale-then-subtract exactly like jax.nn.softmax
        const float amax = __fmul_rn(TEMPF, bd);
        float sum = 0.0f, qp = 0.0f;
        float sv[MAXC];
        for (int i = 0; i < nc; i++) {
            float t = __fadd_rn(__fmul_rn(TEMPF, dcand[i]), -amax);
            float s = __expf(t);
            sv[i] = s;
            sum += s;
            qp  = __fmaf_rn(s, cvs[i], qp);
        }
        const float inv = 1.0f / sum;
        __stcs(quant + row, qp * inv);

        s_meta[tid] = (bk << 16) | nc;
        for (int i = 0; i < nc; i++)
            s_cand[tid][i] = make_int2((int)kks[i], __float_as_int(sv[i] * inv));
    } else {
        s_meta[tid] = 0;   // nc = 0, bk = 0 (row out of range; no stores below)
    }
    __syncthreads();

    // ---------------- Phase 2: warp-per-row dense streaming stores ----------------
    const int lane = tid & 31;
    const int warp = tid >> 5;
    const int k0 = 4 * lane;          // entries k0..k0+3
    const int k1 = 128 + 4 * lane;    // entries k1..k1+3

    for (int rr = warp; rr < RPB; rr += 8) {
        const int grow = row0 + rr;
        if (grow >= rows) break;
        const int meta = s_meta[rr];       // one LDS.32 broadcast
        const int n  = meta & 0xFFFF;
        const int bk = meta >> 16;
        const size_t base = (size_t)grow * KDIM;

        float4 sv0 = make_float4(0.f, 0.f, 0.f, 0.f);
        float4 sv1 = make_float4(0.f, 0.f, 0.f, 0.f);
        for (int i = 0; i < n; i++) {
            const int2  c  = s_cand[rr][i];        // one LDS.64 broadcast
            const int   ki = c.x;
            const float vi = __int_as_float(c.y);
            sv0.x = (ki == k0    ) ? vi : sv0.x;
            sv0.y = (ki == k0 + 1) ? vi : sv0.y;
            sv0.z = (ki == k0 + 2) ? vi : sv0.z;
            sv0.w = (ki == k0 + 3) ? vi : sv0.w;
            sv1.x = (ki == k1    ) ? vi : sv1.x;
            sv1.y = (ki == k1 + 1) ? vi : sv1.y;
            sv1.z = (ki == k1 + 2) ? vi : sv1.z;
            sv1.w = (ki == k1 + 3) ? vi : sv1.w;
        }
        float4 hv0 = make_float4(bk == k0     ? 1.f : 0.f,
                                 bk == k0 + 1 ? 1.f : 0.f,
                                 bk == k0 + 2 ? 1.f : 0.f,
                                 bk == k0 + 3 ? 1.f : 0.f);
        float4 hv1 = make_float4(bk == k1     ? 1.f : 0.f,
                                 bk == k1 + 1 ? 1.f : 0.f,
                                 bk == k1 + 2 ? 1.f : 0.f,
                                 bk == k1 + 3 ? 1.f : 0.f);

        // Streaming (evict-first) stores: output is write-once, never re-read.
        __stcs(reinterpret_cast<float4*>(soft + base) + lane,       sv0);
        __stcs(reinterpret_cast<float4*>(soft + base + 128) + lane, sv1);
        __stcs(reinterpret_cast<float4*>(hard + base) + lane,       hv0);
        __stcs(reinterpret_cast<float4*>(hard + base + 128) + lane, hv1);
    }
}

extern "C" void kernel_launch(void* const* d_in, const int* in_sizes, int n_in,
                              void* d_out, int out_size)
{
    const float* x  = (const float*)d_in[0];   // inputs (1024,512) f32
    const float* cb = (const float*)d_in[1];   // codebook (1,256) f32
    const int rows  = in_sizes[0];             // 524288

    float* out   = (float*)d_out;              // [soft | hard | quantized]
    float* soft  = out;
    float* hard  = out + (size_t)rows * KDIM;
    float* quant = out + 2ull * (size_t)rows * KDIM;

    const int blocks = (rows + RPB - 1) / RPB;
    quantizer_kernel<<<blocks, 256>>>(x, cb, soft, hard, quant, rows);
}